// round 5
// baseline (speedup 1.0000x reference)
#include <cuda_runtime.h>
#include <stdint.h>

// Batched upper-triangular scatter:
//   out[b, r, c] = in[b, r*M - r*(r-1)/2 + (c-r)]  if c >= r, else 0
// M = 1024, TRIU = 524800, B = 128.
//
// 256 MiB read + 512 MiB write per call. Harness times CUDA-graph replays:
// the input re-read each replay can partially persist in L2 (~126 MB).
// Loads carry an evict_last cache-policy descriptor (createpolicy +
// ld.global.nc.L2::cache_hint — the scalar-legal encoding on sm_103a);
// stores are .cs (evict-first) so the single-use write stream doesn't
// flush the resident input.
//
// Config = R1 best (ROWS=4, 256 thr, 8 blocks/SM).

#define MAT_M 1024
#define TRIU_LEN 524800
#define ROWS_PER_BLK 4

__device__ __forceinline__ uint64_t mk_evict_last_policy() {
    uint64_t pol;
    asm volatile("createpolicy.fractional.L2::evict_last.b64 %0, 1.0;" : "=l"(pol));
    return pol;
}

__device__ __forceinline__ float ld_el(const float* p, uint64_t pol) {
    float v;
    asm volatile("ld.global.nc.L2::cache_hint.f32 %0, [%1], %2;"
                 : "=f"(v) : "l"(p), "l"(pol));
    return v;
}

__device__ __forceinline__ float4 ld_el4(const float* p, uint64_t pol) {
    float4 v;
    v.x = ld_el(p + 0, pol);
    v.y = ld_el(p + 1, pol);
    v.z = ld_el(p + 2, pol);
    v.w = ld_el(p + 3, pol);
    return v;
}

__global__ void __launch_bounds__(256, 8)
triu_scatter_kernel(const float* __restrict__ in, float* __restrict__ out)
{
    const int r0 = blockIdx.x * ROWS_PER_BLK;   // 0,4,...,1020
    const int b  = blockIdx.y;                  // 0..B-1
    const int c0 = threadIdx.x << 2;            // 0,4,...,1020

    const float* __restrict__ inb = in + (size_t)b * TRIU_LEN;
    const uint64_t pol = mk_evict_last_policy();

    float4 v[ROWS_PER_BLK];

    // ---- Phase 1: batch all loads (independent -> MLP=4) ----
    #pragma unroll
    for (int j = 0; j < ROWS_PER_BLK; ++j) {
        const int r = r0 + j;
        // rowstart = r*M - r*(r-1)/2, max 524799 (fits int)
        const int rowstart = r * MAT_M - ((r * (r - 1)) >> 1);

        if (c0 >= r) {
            // Fully inside upper triangle: contiguous packed load.
            v[j] = ld_el4(inb + rowstart + (c0 - r), pol);
        } else if (c0 + 3 < r) {
            // Fully below diagonal: pure zero store, no read.
            v[j] = make_float4(0.f, 0.f, 0.f, 0.f);
        } else {
            // Straddles the diagonal (<=1 thread per row).
            float t[4];
            #pragma unroll
            for (int k = 0; k < 4; ++k) {
                const int c = c0 + k;
                t[k] = (c >= r) ? ld_el(inb + rowstart + (c - r), pol) : 0.f;
            }
            v[j] = make_float4(t[0], t[1], t[2], t[3]);
        }
    }

    // ---- Phase 2: aligned streaming (evict-first) float4 stores ----
    const size_t base = (((size_t)b * MAT_M + (size_t)r0) * MAT_M) + (size_t)c0;
    #pragma unroll
    for (int j = 0; j < ROWS_PER_BLK; ++j) {
        __stcs(reinterpret_cast<float4*>(out + base + (size_t)j * MAT_M), v[j]);
    }
}

extern "C" void kernel_launch(void* const* d_in, const int* in_sizes, int n_in,
                              void* d_out, int out_size)
{
    const float* in = (const float*)d_in[0];
    float* out = (float*)d_out;

    const int B = in_sizes[0] / TRIU_LEN;   // 128 for the bench shape

    dim3 grid(MAT_M / ROWS_PER_BLK, B);
    dim3 block(256);
    triu_scatter_kernel<<<grid, block>>>(in, out);
}

// round 6
// speedup vs baseline: 1.0553x; 1.0553x over previous
#include <cuda_runtime.h>
#include <stdint.h>

// Batched upper-triangular scatter:
//   out[b, r, c] = in[b, r*M - r*(r-1)/2 + (c-r)]  if c >= r, else 0
// M = 1024, TRIU = 524800, B = 128.
//
// 256 MiB read + 512 MiB write per call. Harness times CUDA-graph replays:
// input is re-read every replay. R6: loads stay default-policy (__ldg,
// evict-normal -> can persist in ~126MB L2 across replays), stores are
// __stcs (evict-first -> the single-use 512 MiB write stream recycles its
// own L2 lines instead of flushing the resident input).
//
// Codegen otherwise identical to the proven best config
// (ROWS=4, 256 thr, 8 blocks/SM, regs=30, front-batched MLP=4).

#define MAT_M 1024
#define TRIU_LEN 524800
#define ROWS_PER_BLK 4

__device__ __forceinline__ float4 ldg4(const float* p) {
    float4 v;
    v.x = __ldg(p + 0);
    v.y = __ldg(p + 1);
    v.z = __ldg(p + 2);
    v.w = __ldg(p + 3);
    return v;
}

__global__ void __launch_bounds__(256, 8)
triu_scatter_kernel(const float* __restrict__ in, float* __restrict__ out)
{
    const int r0 = blockIdx.x * ROWS_PER_BLK;   // 0,4,...,1020
    const int b  = blockIdx.y;                  // 0..B-1
    const int c0 = threadIdx.x << 2;            // 0,4,...,1020

    const float* __restrict__ inb = in + (size_t)b * TRIU_LEN;

    float4 v[ROWS_PER_BLK];

    // ---- Phase 1: batch all loads (independent -> MLP=4) ----
    #pragma unroll
    for (int j = 0; j < ROWS_PER_BLK; ++j) {
        const int r = r0 + j;
        // rowstart = r*M - r*(r-1)/2, max 524799 (fits int)
        const int rowstart = r * MAT_M - ((r * (r - 1)) >> 1);

        if (c0 >= r) {
            // Fully inside upper triangle: contiguous packed load.
            v[j] = ldg4(inb + rowstart + (c0 - r));
        } else if (c0 + 3 < r) {
            // Fully below diagonal: pure zero store, no read.
            v[j] = make_float4(0.f, 0.f, 0.f, 0.f);
        } else {
            // Straddles the diagonal (<=1 thread per row).
            float t[4];
            #pragma unroll
            for (int k = 0; k < 4; ++k) {
                const int c = c0 + k;
                t[k] = (c >= r) ? __ldg(inb + rowstart + (c - r)) : 0.f;
            }
            v[j] = make_float4(t[0], t[1], t[2], t[3]);
        }
    }

    // ---- Phase 2: aligned streaming (evict-first) float4 stores ----
    const size_t base = (((size_t)b * MAT_M + (size_t)r0) * MAT_M) + (size_t)c0;
    #pragma unroll
    for (int j = 0; j < ROWS_PER_BLK; ++j) {
        __stcs(reinterpret_cast<float4*>(out + base + (size_t)j * MAT_M), v[j]);
    }
}

extern "C" void kernel_launch(void* const* d_in, const int* in_sizes, int n_in,
                              void* d_out, int out_size)
{
    const float* in = (const float*)d_in[0];
    float* out = (float*)d_out;

    const int B = in_sizes[0] / TRIU_LEN;   // 128 for the bench shape

    dim3 grid(MAT_M / ROWS_PER_BLK, B);
    dim3 block(256);
    triu_scatter_kernel<<<grid, block>>>(in, out);
}

// round 7
// speedup vs baseline: 1.0760x; 1.0196x over previous
#include <cuda_runtime.h>
#include <stdint.h>

// Batched upper-triangular scatter:
//   out[b, r, c] = in[b, r*M - r*(r-1)/2 + (c-r)]  if c >= r, else 0
// M = 1024, TRIU = 524800, B = 128.
//
// Pure bandwidth kernel: 256 MiB read + 512 MiB write (both mandatory).
// R7 = champion R2 data path (__ldcs loads front-batched MLP=4, __stcs
// stores) with finer scheduling granularity: 128-thread blocks,
// __launch_bounds__(128,16) -> up to 2048 thr/SM (100% occ) vs 76%
// achieved with 256-thread blocks. Each block: 4 rows x 512-col half-row.

#define MAT_M 1024
#define TRIU_LEN 524800
#define ROWS_PER_BLK 4

__device__ __forceinline__ float4 ldcs4(const float* p) {
    float4 v;
    v.x = __ldcs(p + 0);
    v.y = __ldcs(p + 1);
    v.z = __ldcs(p + 2);
    v.w = __ldcs(p + 3);
    return v;
}

__global__ void __launch_bounds__(128, 16)
triu_scatter_kernel(const float* __restrict__ in, float* __restrict__ out)
{
    const int half = blockIdx.x;                       // 0..1 (column half)
    const int r0   = blockIdx.y * ROWS_PER_BLK;        // 0,4,...,1020
    const int b    = blockIdx.z;                       // 0..B-1
    const int c0   = (half * 128 + threadIdx.x) << 2;  // 0,4,...,1020

    const float* __restrict__ inb = in + (size_t)b * TRIU_LEN;

    float4 v[ROWS_PER_BLK];

    // ---- Phase 1: batch all loads (independent -> MLP=4) ----
    #pragma unroll
    for (int j = 0; j < ROWS_PER_BLK; ++j) {
        const int r = r0 + j;
        // rowstart = r*M - r*(r-1)/2, max 524799 (fits int)
        const int rowstart = r * MAT_M - ((r * (r - 1)) >> 1);

        if (c0 >= r) {
            // Fully inside upper triangle: contiguous packed load.
            v[j] = ldcs4(inb + rowstart + (c0 - r));
        } else if (c0 + 3 < r) {
            // Fully below diagonal: pure zero store, no read.
            v[j] = make_float4(0.f, 0.f, 0.f, 0.f);
        } else {
            // Straddles the diagonal (<=1 thread per row).
            float t[4];
            #pragma unroll
            for (int k = 0; k < 4; ++k) {
                const int c = c0 + k;
                t[k] = (c >= r) ? __ldcs(inb + rowstart + (c - r)) : 0.f;
            }
            v[j] = make_float4(t[0], t[1], t[2], t[3]);
        }
    }

    // ---- Phase 2: aligned streaming (evict-first) float4 stores ----
    const size_t base = (((size_t)b * MAT_M + (size_t)r0) * MAT_M) + (size_t)c0;
    #pragma unroll
    for (int j = 0; j < ROWS_PER_BLK; ++j) {
        __stcs(reinterpret_cast<float4*>(out + base + (size_t)j * MAT_M), v[j]);
    }
}

extern "C" void kernel_launch(void* const* d_in, const int* in_sizes, int n_in,
                              void* d_out, int out_size)
{
    const float* in = (const float*)d_in[0];
    float* out = (float*)d_out;

    const int B = in_sizes[0] / TRIU_LEN;   // 128 for the bench shape

    dim3 grid(2, MAT_M / ROWS_PER_BLK, B);
    dim3 block(128);
    triu_scatter_kernel<<<grid, block>>>(in, out);
}